// round 12
// baseline (speedup 1.0000x reference)
#include <cuda_runtime.h>

#define FULL_MASK 0xffffffffu

// Tree output: [B=16][D=256] (head h occupies channels h*32..h*32+31)
__device__ float g_tv[16 * 256];

// ---------------------------------------------------------------------------
// Tree node step (R4, proven): stage W[node] into a warp-private padded smem
// slot (stride-33 rows -> conflict-free LDS), shuffle-broadcast matmul + LIF.
// ---------------------------------------------------------------------------
__device__ __forceinline__ void node_step(
    float& xk, float& xv, int node, int lane,
    float* __restrict__ Wslot,
    const float* __restrict__ W,
    const float* __restrict__ bvec, const float* __restrict__ thr,
    const float* __restrict__ tau,  const float* __restrict__ vres)
{
    const float4* __restrict__ Wn = reinterpret_cast<const float4*>(W + node * 1024);
#pragma unroll
    for (int i = lane; i < 256; i += 32) {
        const float4 wv = Wn[i];
        const int o  = i >> 3;
        const int d4 = (i & 7) << 2;
        float* dst = &Wslot[o * 33 + d4];
        dst[0] = wv.x; dst[1] = wv.y; dst[2] = wv.z; dst[3] = wv.w;
    }
    __syncwarp();

    const float* __restrict__ wrow = Wslot + lane * 33;
    float ok = 0.f, ov = 0.f;
#pragma unroll
    for (int d = 0; d < 32; ++d) {
        const float ak = __shfl_sync(FULL_MASK, xk, d);
        const float av = __shfl_sync(FULL_MASK, xv, d);
        const float w  = wrow[d];
        ok = fmaf(ak, w, ok);
        ov = fmaf(av, w, ov);
    }
    const float bl = __ldg(&bvec[node * 32 + lane]);
    ok += bl;
    ov += bl;

    const float th = __ldg(&thr[node * 32 + lane]);
    const float ta = __ldg(&tau[node * 32 + lane]);
    const float vr = __ldg(&vres[node * 32 + lane]);
    const float sk = (xk >= th) ? 1.f : 0.f;
    const float va = xk * (1.f - sk) + vr * sk;
    const float v2 = fmaf(ta, va, xv);
    const float sv = (v2 >= th) ? 1.f : 0.f;

    xk = ok * sk;
    xv = ov * sv;
}

// ---------------------------------------------------------------------------
// Kernel A: LIF tree. One block per (batch, head): 128 blocks x 256 threads.
// Warp l owns node l of the current level (exact R4 structure).
// ---------------------------------------------------------------------------
__global__ __launch_bounds__(256) void tree_kernel(
    const float* __restrict__ key_value,
    const float* __restrict__ W,
    const float* __restrict__ bvec,
    const float* __restrict__ thr,
    const float* __restrict__ tau,
    const float* __restrict__ vres)
{
    __shared__ float Wslots[8][1056];
    __shared__ float ks[8][32];
    __shared__ float vs[8][32];

    const int tid  = threadIdx.x;
    const int lane = tid & 31;
    const int w    = tid >> 5;
    const int b    = blockIdx.x >> 3;
    const int h    = blockIdx.x & 7;

    float* Wslot = Wslots[w];

    float xk = __ldg(&key_value[(b * 16 + w) * 256 + h * 32 + lane]);
    float xv = xk;

    // level 1: nodes 7..14 (8 warps, 8 nodes in parallel)
    node_step(xk, xv, 7 + w, lane, Wslot, W, bvec, thr, tau, vres);
    ks[w][lane] = xk; vs[w][lane] = xv;
    __syncthreads();

    // level 2: nodes 3..6
    if (w < 4) {
        xk = 0.5f * (ks[2 * w][lane] + ks[2 * w + 1][lane]);
        xv = 0.5f * (vs[2 * w][lane] + vs[2 * w + 1][lane]);
        node_step(xk, xv, 3 + w, lane, Wslot, W, bvec, thr, tau, vres);
    }
    __syncthreads();
    if (w < 4) { ks[w][lane] = xk; vs[w][lane] = xv; }
    __syncthreads();

    // level 3: nodes 1..2
    if (w < 2) {
        xk = 0.5f * (ks[2 * w][lane] + ks[2 * w + 1][lane]);
        xv = 0.5f * (vs[2 * w][lane] + vs[2 * w + 1][lane]);
        node_step(xk, xv, 1 + w, lane, Wslot, W, bvec, thr, tau, vres);
    }
    __syncthreads();
    if (w < 2) { ks[w][lane] = xk; vs[w][lane] = xv; }
    __syncthreads();

    // level 4: root node 0; softmax over single node == 1 -> tv broadcast
    if (w == 0) {
        xk = 0.5f * (ks[0][lane] + ks[1][lane]);
        xv = 0.5f * (vs[0][lane] + vs[1][lane]);
        node_step(xk, xv, 0, lane, Wslot, W, bvec, thr, tau, vres);
        g_tv[b * 256 + h * 32 + lane] = xv;
    }
}

// ---------------------------------------------------------------------------
// Kernel B: fused residual-add + LayerNorm. Winning per-warp config
// (2 rows/warp) but 512 threads/block -> HALF the blocks (4096): the
// cross-round ledger shows total time tracks the second kernel's block count
// (~4us between 8192 and 4096 one-shot blocks), not its isolated ncu time.
// ---------------------------------------------------------------------------
__global__ __launch_bounds__(512) void ln_kernel(
    const float* __restrict__ query,
    const float* __restrict__ gamma,
    const float* __restrict__ beta,
    float* __restrict__ out)
{
    const int  lane = threadIdx.x & 31;
    const long long warp = (long long)blockIdx.x * 16 + (threadIdx.x >> 5);
    const long long r0 = warp * 2;          // rows r0, r0+1 (same batch)
    const int  b = (int)(r0 >> 13);

    const float4* __restrict__ q0r = reinterpret_cast<const float4*>(query) + r0 * 64;
    const float4* __restrict__ q1r = q0r + 64;
    const float4* __restrict__ tvr = reinterpret_cast<const float4*>(g_tv) + b * 64;
    const float4* __restrict__ g4  = reinterpret_cast<const float4*>(gamma);
    const float4* __restrict__ be4 = reinterpret_cast<const float4*>(beta);

    // 4 independent row loads in flight
    const float4 qa0 = __ldg(&q0r[lane]);
    const float4 qa1 = __ldg(&q0r[lane + 32]);
    const float4 qb0 = __ldg(&q1r[lane]);
    const float4 qb1 = __ldg(&q1r[lane + 32]);
    const float4 t0  = tvr[lane];
    const float4 t1  = tvr[lane + 32];

    float4 xa0 = make_float4(qa0.x + t0.x, qa0.y + t0.y, qa0.z + t0.z, qa0.w + t0.w);
    float4 xa1 = make_float4(qa1.x + t1.x, qa1.y + t1.y, qa1.z + t1.z, qa1.w + t1.w);
    float4 xb0 = make_float4(qb0.x + t0.x, qb0.y + t0.y, qb0.z + t0.z, qb0.w + t0.w);
    float4 xb1 = make_float4(qb1.x + t1.x, qb1.y + t1.y, qb1.z + t1.z, qb1.w + t1.w);

    float sa  = xa0.x + xa0.y + xa0.z + xa0.w + xa1.x + xa1.y + xa1.z + xa1.w;
    float ssa = xa0.x*xa0.x + xa0.y*xa0.y + xa0.z*xa0.z + xa0.w*xa0.w
              + xa1.x*xa1.x + xa1.y*xa1.y + xa1.z*xa1.z + xa1.w*xa1.w;
    float sb  = xb0.x + xb0.y + xb0.z + xb0.w + xb1.x + xb1.y + xb1.z + xb1.w;
    float ssb = xb0.x*xb0.x + xb0.y*xb0.y + xb0.z*xb0.z + xb0.w*xb0.w
              + xb1.x*xb1.x + xb1.y*xb1.y + xb1.z*xb1.z + xb1.w*xb1.w;

#pragma unroll
    for (int off = 16; off > 0; off >>= 1) {
        sa  += __shfl_xor_sync(FULL_MASK, sa,  off);
        ssa += __shfl_xor_sync(FULL_MASK, ssa, off);
        sb  += __shfl_xor_sync(FULL_MASK, sb,  off);
        ssb += __shfl_xor_sync(FULL_MASK, ssb, off);
    }

    const float ma   = sa * (1.f / 256.f);
    const float inva = rsqrtf(ssa * (1.f / 256.f) - ma * ma + 1e-5f);
    const float mb   = sb * (1.f / 256.f);
    const float invb = rsqrtf(ssb * (1.f / 256.f) - mb * mb + 1e-5f);

    const float4 g0 = __ldg(&g4[lane]);
    const float4 g1 = __ldg(&g4[lane + 32]);
    const float4 b0 = __ldg(&be4[lane]);
    const float4 b1 = __ldg(&be4[lane + 32]);

    float4 ya0, ya1, yb0, yb1;
    ya0.x = fmaf((xa0.x - ma) * inva, g0.x, b0.x);
    ya0.y = fmaf((xa0.y - ma) * inva, g0.y, b0.y);
    ya0.z = fmaf((xa0.z - ma) * inva, g0.z, b0.z);
    ya0.w = fmaf((xa0.w - ma) * inva, g0.w, b0.w);
    ya1.x = fmaf((xa1.x - ma) * inva, g1.x, b1.x);
    ya1.y = fmaf((xa1.y - ma) * inva, g1.y, b1.y);
    ya1.z = fmaf((xa1.z - ma) * inva, g1.z, b1.z);
    ya1.w = fmaf((xa1.w - ma) * inva, g1.w, b1.w);
    yb0.x = fmaf((xb0.x - mb) * invb, g0.x, b0.x);
    yb0.y = fmaf((xb0.y - mb) * invb, g0.y, b0.y);
    yb0.z = fmaf((xb0.z - mb) * invb, g0.z, b0.z);
    yb0.w = fmaf((xb0.w - mb) * invb, g0.w, b0.w);
    yb1.x = fmaf((xb1.x - mb) * invb, g1.x, b1.x);
    yb1.y = fmaf((xb1.y - mb) * invb, g1.y, b1.y);
    yb1.z = fmaf((xb1.z - mb) * invb, g1.z, b1.z);
    yb1.w = fmaf((xb1.w - mb) * invb, g1.w, b1.w);

    float4* __restrict__ o0 = reinterpret_cast<float4*>(out) + r0 * 64;
    float4* __restrict__ o1 = o0 + 64;
    o0[lane]      = ya0;
    o0[lane + 32] = ya1;
    o1[lane]      = yb0;
    o1[lane + 32] = yb1;
}

// ---------------------------------------------------------------------------
// Inputs (metadata order): query, key_value, W, b, thr, tau, vres, gamma, beta
// Output: float32, 16*8192*256 elements
// ---------------------------------------------------------------------------
extern "C" void kernel_launch(void* const* d_in, const int* in_sizes, int n_in,
                              void* d_out, int out_size)
{
    (void)in_sizes; (void)n_in; (void)out_size;
    const float* query = (const float*)d_in[0];
    const float* kv    = (const float*)d_in[1];
    const float* W     = (const float*)d_in[2];
    const float* bvec  = (const float*)d_in[3];
    const float* thr   = (const float*)d_in[4];
    const float* tau   = (const float*)d_in[5];
    const float* vres  = (const float*)d_in[6];
    const float* gamma = (const float*)d_in[7];
    const float* beta  = (const float*)d_in[8];
    float* out = (float*)d_out;

    // Kernel A: one block per (batch, head); warp = node within level
    tree_kernel<<<128, 256>>>(kv, W, bvec, thr, tau, vres);

    // Kernel B: 131072 rows, 2 rows/warp, 16 warps/block -> 4096 blocks
    ln_kernel<<<4096, 512>>>(query, gamma, beta, out);
}

// round 13
// speedup vs baseline: 1.0833x; 1.0833x over previous
#include <cuda_runtime.h>

#define FULL_MASK 0xffffffffu

// Tree output: [B=16][D=256] (head h occupies channels h*32..h*32+31)
__device__ float g_tv[16 * 256];

// ---------------------------------------------------------------------------
// Register-resident node step: W rows already prefetched into wreg[8]
// (lane o holds W[node][o][0..31]); shuffle-broadcast matmul + LIF.
// ---------------------------------------------------------------------------
__device__ __forceinline__ void node_step_reg(
    float& xk, float& xv,
    const float4* wreg,              // 8 x float4 = this lane's W row
    float bl, float th, float ta, float vr)
{
    float ok = 0.f, ov = 0.f;
#pragma unroll
    for (int c = 0; c < 8; ++c) {
        const float4 wv = wreg[c];
        float ak, av;
        ak = __shfl_sync(FULL_MASK, xk, 4 * c + 0);
        av = __shfl_sync(FULL_MASK, xv, 4 * c + 0);
        ok = fmaf(ak, wv.x, ok);  ov = fmaf(av, wv.x, ov);
        ak = __shfl_sync(FULL_MASK, xk, 4 * c + 1);
        av = __shfl_sync(FULL_MASK, xv, 4 * c + 1);
        ok = fmaf(ak, wv.y, ok);  ov = fmaf(av, wv.y, ov);
        ak = __shfl_sync(FULL_MASK, xk, 4 * c + 2);
        av = __shfl_sync(FULL_MASK, xv, 4 * c + 2);
        ok = fmaf(ak, wv.z, ok);  ov = fmaf(av, wv.z, ov);
        ak = __shfl_sync(FULL_MASK, xk, 4 * c + 3);
        av = __shfl_sync(FULL_MASK, xv, 4 * c + 3);
        ok = fmaf(ak, wv.w, ok);  ov = fmaf(av, wv.w, ov);
    }
    ok += bl;
    ov += bl;

    const float sk = (xk >= th) ? 1.f : 0.f;
    const float va = xk * (1.f - sk) + vr * sk;
    const float v2 = fmaf(ta, va, xv);
    const float sv = (v2 >= th) ? 1.f : 0.f;

    xk = ok * sk;
    xv = ov * sv;
}

// ---------------------------------------------------------------------------
// Kernel A: LIF tree (R11 register-prefetch version — shortest critical path).
// One block per (batch, head): 128 blocks x 256 threads. Level->warp map
// (<=2 nodes per warp): L1 nodes 7..14 -> warps 0..7, L2 nodes 3..6 -> w0..3,
// L3 nodes 1..2 -> w4..5, L4 node 0 -> w6. Each warp prefetches BOTH its
// nodes' W rows + params at kernel start: ONE exposed DRAM latency, then the
// whole tree is register/shfl compute with only 3 cheap barriers.
// ---------------------------------------------------------------------------
__global__ __launch_bounds__(256) void tree_kernel(
    const float* __restrict__ key_value,
    const float* __restrict__ W,
    const float* __restrict__ bvec,
    const float* __restrict__ thr,
    const float* __restrict__ tau,
    const float* __restrict__ vres)
{
    __shared__ float ks1[8][32], vs1[8][32];
    __shared__ float ks2[4][32], vs2[4][32];
    __shared__ float ks3[2][32], vs3[2][32];

    const int tid  = threadIdx.x;
    const int lane = tid & 31;
    const int w    = tid >> 5;
    const int b    = blockIdx.x >> 3;
    const int h    = blockIdx.x & 7;

    const int nodeA = 7 + w;                         // level-1 node
    const int nodeB_tbl[8] = {3, 4, 5, 6, 1, 2, 0, 0};
    const int nodeB = nodeB_tbl[w];                  // later-level node (w7 unused)

    const float4* __restrict__ WA =
        reinterpret_cast<const float4*>(W + nodeA * 1024) + lane * 8;
    const float4* __restrict__ WB =
        reinterpret_cast<const float4*>(W + nodeB * 1024) + lane * 8;

    float xk = __ldg(&key_value[(b * 16 + w) * 256 + h * 32 + lane]);
    float xv = xk;

    float4 wrA[8], wrB[8];
#pragma unroll
    for (int c = 0; c < 8; ++c) wrA[c] = __ldg(&WA[c]);
#pragma unroll
    for (int c = 0; c < 8; ++c) wrB[c] = __ldg(&WB[c]);

    const float blA = __ldg(&bvec[nodeA * 32 + lane]);
    const float thA = __ldg(&thr [nodeA * 32 + lane]);
    const float taA = __ldg(&tau [nodeA * 32 + lane]);
    const float vrA = __ldg(&vres[nodeA * 32 + lane]);
    const float blB = __ldg(&bvec[nodeB * 32 + lane]);
    const float thB = __ldg(&thr [nodeB * 32 + lane]);
    const float taB = __ldg(&tau [nodeB * 32 + lane]);
    const float vrB = __ldg(&vres[nodeB * 32 + lane]);

    // level 1: nodes 7..14, all 8 warps
    node_step_reg(xk, xv, wrA, blA, thA, taA, vrA);
    ks1[w][lane] = xk; vs1[w][lane] = xv;
    __syncthreads();

    // level 2: nodes 3..6 -> warps 0..3
    if (w < 4) {
        xk = 0.5f * (ks1[2 * w][lane] + ks1[2 * w + 1][lane]);
        xv = 0.5f * (vs1[2 * w][lane] + vs1[2 * w + 1][lane]);
        node_step_reg(xk, xv, wrB, blB, thB, taB, vrB);
        ks2[w][lane] = xk; vs2[w][lane] = xv;
    }
    __syncthreads();

    // level 3: nodes 1..2 -> warps 4..5
    if (w == 4 || w == 5) {
        const int j = w - 4;
        xk = 0.5f * (ks2[2 * j][lane] + ks2[2 * j + 1][lane]);
        xv = 0.5f * (vs2[2 * j][lane] + vs2[2 * j + 1][lane]);
        node_step_reg(xk, xv, wrB, blB, thB, taB, vrB);
        ks3[j][lane] = xk; vs3[j][lane] = xv;
    }
    __syncthreads();

    // level 4: node 0 -> warp 6
    if (w == 6) {
        xk = 0.5f * (ks3[0][lane] + ks3[1][lane]);
        xv = 0.5f * (vs3[0][lane] + vs3[1][lane]);
        node_step_reg(xk, xv, wrB, blB, thB, taB, vrB);
        // softmax over a single tree node == 1.0 -> attn_out = tree_v broadcast
        g_tv[b * 256 + h * 32 + lane] = xv;
    }
}

// ---------------------------------------------------------------------------
// Kernel B: fused residual-add + LayerNorm — EXACT configuration from the
// 47.6us record (R4): one warp per FOUR rows, 4096 blocks x 256 threads.
// ---------------------------------------------------------------------------
__global__ __launch_bounds__(256) void ln_kernel(
    const float* __restrict__ query,
    const float* __restrict__ gamma,
    const float* __restrict__ beta,
    float* __restrict__ out)
{
    const int  lane = threadIdx.x & 31;
    const long long warp = (long long)blockIdx.x * 8 + (threadIdx.x >> 5);
    const long long r0 = warp * 4;           // rows r0..r0+3 (same batch)
    const int  b = (int)(r0 >> 13);

    const float4* __restrict__ qr  = reinterpret_cast<const float4*>(query) + r0 * 64;
    const float4* __restrict__ tvr = reinterpret_cast<const float4*>(g_tv) + b * 64;
    const float4* __restrict__ g4  = reinterpret_cast<const float4*>(gamma);
    const float4* __restrict__ be4 = reinterpret_cast<const float4*>(beta);

    // 8 independent row loads in flight
    float4 q[4][2];
#pragma unroll
    for (int r = 0; r < 4; ++r) {
        q[r][0] = __ldcs(&qr[r * 64 + lane]);
        q[r][1] = __ldcs(&qr[r * 64 + lane + 32]);
    }
    const float4 t0 = tvr[lane];
    const float4 t1 = tvr[lane + 32];

    float s[4], ss[4];
#pragma unroll
    for (int r = 0; r < 4; ++r) {
        float4 x0 = make_float4(q[r][0].x + t0.x, q[r][0].y + t0.y,
                                q[r][0].z + t0.z, q[r][0].w + t0.w);
        float4 x1 = make_float4(q[r][1].x + t1.x, q[r][1].y + t1.y,
                                q[r][1].z + t1.z, q[r][1].w + t1.w);
        q[r][0] = x0; q[r][1] = x1;
        s[r]  = x0.x + x0.y + x0.z + x0.w + x1.x + x1.y + x1.z + x1.w;
        ss[r] = x0.x*x0.x + x0.y*x0.y + x0.z*x0.z + x0.w*x0.w
              + x1.x*x1.x + x1.y*x1.y + x1.z*x1.z + x1.w*x1.w;
    }

#pragma unroll
    for (int off = 16; off > 0; off >>= 1) {
#pragma unroll
        for (int r = 0; r < 4; ++r) {
            s[r]  += __shfl_xor_sync(FULL_MASK, s[r],  off);
            ss[r] += __shfl_xor_sync(FULL_MASK, ss[r], off);
        }
    }

    const float4 g0 = __ldg(&g4[lane]);
    const float4 g1 = __ldg(&g4[lane + 32]);
    const float4 b0 = __ldg(&be4[lane]);
    const float4 b1 = __ldg(&be4[lane + 32]);

    float4* __restrict__ o4 = reinterpret_cast<float4*>(out) + r0 * 64;
#pragma unroll
    for (int r = 0; r < 4; ++r) {
        const float m   = s[r] * (1.f / 256.f);
        const float inv = rsqrtf(ss[r] * (1.f / 256.f) - m * m + 1e-5f);
        float4 y0, y1;
        y0.x = fmaf((q[r][0].x - m) * inv, g0.x, b0.x);
        y0.y = fmaf((q[r][0].y - m) * inv, g0.y, b0.y);
        y0.z = fmaf((q[r][0].z - m) * inv, g0.z, b0.z);
        y0.w = fmaf((q[r][0].w - m) * inv, g0.w, b0.w);
        y1.x = fmaf((q[r][1].x - m) * inv, g1.x, b1.x);
        y1.y = fmaf((q[r][1].y - m) * inv, g1.y, b1.y);
        y1.z = fmaf((q[r][1].z - m) * inv, g1.z, b1.z);
        y1.w = fmaf((q[r][1].w - m) * inv, g1.w, b1.w);
        __stcs(&o4[r * 64 + lane],      y0);
        __stcs(&o4[r * 64 + lane + 32], y1);
    }
}

// ---------------------------------------------------------------------------
// Inputs (metadata order): query, key_value, W, b, thr, tau, vres, gamma, beta
// Output: float32, 16*8192*256 elements
// ---------------------------------------------------------------------------
extern "C" void kernel_launch(void* const* d_in, const int* in_sizes, int n_in,
                              void* d_out, int out_size)
{
    (void)in_sizes; (void)n_in; (void)out_size;
    const float* query = (const float*)d_in[0];
    const float* kv    = (const float*)d_in[1];
    const float* W     = (const float*)d_in[2];
    const float* bvec  = (const float*)d_in[3];
    const float* thr   = (const float*)d_in[4];
    const float* tau   = (const float*)d_in[5];
    const float* vres  = (const float*)d_in[6];
    const float* gamma = (const float*)d_in[7];
    const float* beta  = (const float*)d_in[8];
    float* out = (float*)d_out;

    // Kernel A: one block per (batch, head); <=2 nodes/warp, W in registers
    tree_kernel<<<128, 256>>>(kv, W, bvec, thr, tau, vres);

    // Kernel B: 131072 rows, 4 rows/warp, 8 warps/block -> 4096 blocks
    ln_kernel<<<4096, 256>>>(query, gamma, beta, out);
}

// round 14
// speedup vs baseline: 1.0961x; 1.0118x over previous
#include <cuda_runtime.h>

#define FULL_MASK 0xffffffffu

// Scratch for tree_v, laid out as [B=16][D=256] (head h occupies channels h*32..h*32+31)
__device__ float g_tv[16 * 256];

// ---------------------------------------------------------------------------
// Kernel A: LIF tree. One block per (batch, head): 128 blocks x 256 threads.
// Warp l owns node l of the current level (level1: 8 warps run 8 nodes
// concurrently). Each warp stages ONLY its node's W into a warp-private
// padded smem slot (stride-33 rows -> conflict-free LDS; __syncwarp only).
// Merges between levels go through a small smem buffer + __syncthreads.
// ---------------------------------------------------------------------------
__device__ __forceinline__ void node_step(
    float& xk, float& xv, int node, int lane,
    float* __restrict__ Wslot,
    const float* __restrict__ W,
    const float* __restrict__ bvec, const float* __restrict__ thr,
    const float* __restrict__ tau,  const float* __restrict__ vres)
{
    // stage W[node] (32x32) into Wslot with padding: 8 float4 per lane, coalesced
    const float4* __restrict__ Wn = reinterpret_cast<const float4*>(W + node * 1024);
#pragma unroll
    for (int i = lane; i < 256; i += 32) {
        const float4 w = Wn[i];
        const int o  = i >> 3;
        const int d4 = (i & 7) << 2;
        float* dst = &Wslot[o * 33 + d4];
        dst[0] = w.x; dst[1] = w.y; dst[2] = w.z; dst[3] = w.w;
    }
    __syncwarp();

    const float* __restrict__ wrow = Wslot + lane * 33;
    float ok = 0.f, ov = 0.f;
#pragma unroll
    for (int d = 0; d < 32; ++d) {
        const float ak = __shfl_sync(FULL_MASK, xk, d);
        const float av = __shfl_sync(FULL_MASK, xv, d);
        const float w  = wrow[d];
        ok = fmaf(ak, w, ok);
        ov = fmaf(av, w, ov);
    }
    const float bl = __ldg(&bvec[node * 32 + lane]);
    ok += bl;
    ov += bl;

    const float th = __ldg(&thr[node * 32 + lane]);
    const float ta = __ldg(&tau[node * 32 + lane]);
    const float vr = __ldg(&vres[node * 32 + lane]);
    const float sk = (xk >= th) ? 1.f : 0.f;
    const float va = xk * (1.f - sk) + vr * sk;
    const float v2 = fmaf(ta, va, xv);
    const float sv = (v2 >= th) ? 1.f : 0.f;

    xk = ok * sk;
    xv = ov * sv;
}

__global__ __launch_bounds__(256) void tree_kernel(
    const float* __restrict__ key_value,
    const float* __restrict__ W,
    const float* __restrict__ bvec,
    const float* __restrict__ thr,
    const float* __restrict__ tau,
    const float* __restrict__ vres)
{
    __shared__ float Wslots[8][1056];   // warp-private staging, 33792 B
    __shared__ float ks[8][32];
    __shared__ float vs[8][32];

    const int tid  = threadIdx.x;
    const int lane = tid & 31;
    const int w    = tid >> 5;          // warp id = node index within level
    const int b    = blockIdx.x >> 3;
    const int h    = blockIdx.x & 7;

    float* Wslot = Wslots[w];

    // leaf w: key_value[b, w, h*32 + lane]
    float xk = __ldg(&key_value[(b * 16 + w) * 256 + h * 32 + lane]);
    float xv = xk;

    // ---- level 1: 8 nodes (7..14), all warps active -------------------------
    node_step(xk, xv, 7 + w, lane, Wslot, W, bvec, thr, tau, vres);
    ks[w][lane] = xk; vs[w][lane] = xv;
    __syncthreads();

    // ---- level 2: 4 nodes (3..6) --------------------------------------------
    if (w < 4) {
        xk = 0.5f * (ks[2 * w][lane] + ks[2 * w + 1][lane]);
        xv = 0.5f * (vs[2 * w][lane] + vs[2 * w + 1][lane]);
        node_step(xk, xv, 3 + w, lane, Wslot, W, bvec, thr, tau, vres);
    }
    __syncthreads();
    if (w < 4) { ks[w][lane] = xk; vs[w][lane] = xv; }
    __syncthreads();

    // ---- level 3: 2 nodes (1..2) --------------------------------------------
    if (w < 2) {
        xk = 0.5f * (ks[2 * w][lane] + ks[2 * w + 1][lane]);
        xv = 0.5f * (vs[2 * w][lane] + vs[2 * w + 1][lane]);
        node_step(xk, xv, 1 + w, lane, Wslot, W, bvec, thr, tau, vres);
    }
    __syncthreads();
    if (w < 2) { ks[w][lane] = xk; vs[w][lane] = xv; }
    __syncthreads();

    // ---- level 4: root node 0 ------------------------------------------------
    if (w == 0) {
        xk = 0.5f * (ks[0][lane] + ks[1][lane]);
        xv = 0.5f * (vs[0][lane] + vs[1][lane]);
        node_step(xk, xv, 0, lane, Wslot, W, bvec, thr, tau, vres);
        // softmax over a single tree node == 1.0 -> attn_out = tree_v broadcast
        g_tv[b * 256 + h * 32 + lane] = xv;
    }
}

// ---------------------------------------------------------------------------
// Kernel B: fused residual-add + LayerNorm. One warp per FOUR rows (D=256):
// 8 independent LDG.128 in flight per warp. 268 MB mandatory HBM traffic.
// ---------------------------------------------------------------------------
__global__ __launch_bounds__(256) void ln_kernel(
    const float* __restrict__ query,
    const float* __restrict__ gamma,
    const float* __restrict__ beta,
    float* __restrict__ out)
{
    const int  lane = threadIdx.x & 31;
    const long long warp = (long long)blockIdx.x * 8 + (threadIdx.x >> 5);
    const long long r0 = warp * 4;           // rows r0..r0+3 (same batch)
    const int  b = (int)(r0 >> 13);

    const float4* __restrict__ qr  = reinterpret_cast<const float4*>(query) + r0 * 64;
    const float4* __restrict__ tvr = reinterpret_cast<const float4*>(g_tv) + b * 64;
    const float4* __restrict__ g4  = reinterpret_cast<const float4*>(gamma);
    const float4* __restrict__ be4 = reinterpret_cast<const float4*>(beta);

    // 8 independent streaming row loads in flight
    float4 q[4][2];
#pragma unroll
    for (int r = 0; r < 4; ++r) {
        q[r][0] = __ldcs(&qr[r * 64 + lane]);
        q[r][1] = __ldcs(&qr[r * 64 + lane + 32]);
    }
    const float4 t0 = tvr[lane];
    const float4 t1 = tvr[lane + 32];

    float s[4], ss[4];
#pragma unroll
    for (int r = 0; r < 4; ++r) {
        float4 x0 = make_float4(q[r][0].x + t0.x, q[r][0].y + t0.y,
                                q[r][0].z + t0.z, q[r][0].w + t0.w);
        float4 x1 = make_float4(q[r][1].x + t1.x, q[r][1].y + t1.y,
                                q[r][1].z + t1.z, q[r][1].w + t1.w);
        q[r][0] = x0; q[r][1] = x1;
        s[r]  = x0.x + x0.y + x0.z + x0.w + x1.x + x1.y + x1.z + x1.w;
        ss[r] = x0.x*x0.x + x0.y*x0.y + x0.z*x0.z + x0.w*x0.w
              + x1.x*x1.x + x1.y*x1.y + x1.z*x1.z + x1.w*x1.w;
    }

#pragma unroll
    for (int off = 16; off > 0; off >>= 1) {
#pragma unroll
        for (int r = 0; r < 4; ++r) {
            s[r]  += __shfl_xor_sync(FULL_MASK, s[r],  off);
            ss[r] += __shfl_xor_sync(FULL_MASK, ss[r], off);
        }
    }

    const float4 g0 = __ldg(&g4[lane]);
    const float4 g1 = __ldg(&g4[lane + 32]);
    const float4 b0 = __ldg(&be4[lane]);
    const float4 b1 = __ldg(&be4[lane + 32]);

    float4* __restrict__ o4 = reinterpret_cast<float4*>(out) + r0 * 64;
#pragma unroll
    for (int r = 0; r < 4; ++r) {
        const float m   = s[r] * (1.f / 256.f);
        const float inv = rsqrtf(ss[r] * (1.f / 256.f) - m * m + 1e-5f);
        float4 y0, y1;
        y0.x = fmaf((q[r][0].x - m) * inv, g0.x, b0.x);
        y0.y = fmaf((q[r][0].y - m) * inv, g0.y, b0.y);
        y0.z = fmaf((q[r][0].z - m) * inv, g0.z, b0.z);
        y0.w = fmaf((q[r][0].w - m) * inv, g0.w, b0.w);
        y1.x = fmaf((q[r][1].x - m) * inv, g1.x, b1.x);
        y1.y = fmaf((q[r][1].y - m) * inv, g1.y, b1.y);
        y1.z = fmaf((q[r][1].z - m) * inv, g1.z, b1.z);
        y1.w = fmaf((q[r][1].w - m) * inv, g1.w, b1.w);
        __stcs(&o4[r * 64 + lane],      y0);
        __stcs(&o4[r * 64 + lane + 32], y1);
    }
}

// ---------------------------------------------------------------------------
// Inputs (metadata order): query, key_value, W, b, thr, tau, vres, gamma, beta
// Output: float32, 16*8192*256 elements
// ---------------------------------------------------------------------------
extern "C" void kernel_launch(void* const* d_in, const int* in_sizes, int n_in,
                              void* d_out, int out_size)
{
    (void)in_sizes; (void)n_in; (void)out_size;
    const float* query = (const float*)d_in[0];
    const float* kv    = (const float*)d_in[1];
    const float* W     = (const float*)d_in[2];
    const float* bvec  = (const float*)d_in[3];
    const float* thr   = (const float*)d_in[4];
    const float* tau   = (const float*)d_in[5];
    const float* vres  = (const float*)d_in[6];
    const float* gamma = (const float*)d_in[7];
    const float* beta  = (const float*)d_in[8];
    float* out = (float*)d_out;

    // Kernel A: one block per (batch, head); warp = node within level
    tree_kernel<<<128, 256>>>(kv, W, bvec, thr, tau, vres);

    // Kernel B: 131072 rows, 4 rows/warp, 8 warps/block -> 4096 blocks
    ln_kernel<<<4096, 256>>>(query, gamma, beta, out);
}